// round 6
// baseline (speedup 1.0000x reference)
#include <cuda_runtime.h>
#include <cstdint>

// ---------------- config ----------------
#define CTAS        2048
#define THREADS     256
#define PAIRS       4               // 8 warps = 4 pairs
#define UNIT_ROWS   16
#define UNIT_BYTES  4096
#define NSLOTS      4
#define NUNITS      8               // units per pair: 4 pairs * 128 rows * 2048 = 2^20

// smem layout (bytes)
#define FB_BYTES    16384           // fragment-major W
#define SMEM_RING   FB_BYTES
#define RING_BYTES  (NSLOTS * UNIT_BYTES)            // 16384 per pair
#define SMEM_PB     (SMEM_RING + PAIRS * RING_BYTES) // 81920
#define PB_BYTES    128             // 32 floats per pair per parity
#define SMEM_TOTAL  (SMEM_PB + PAIRS * 2 * PB_BYTES) // 82944

// ---------------- math constants ----------------
#define C_SCALE_L2E  4.3280851227f   // 3 * log2(e)
#define C_CLAMP_L2E 14.4269504089f   // 10 * log2(e)
#define C_LN2        0.6931471806f

// ---------------- helpers ----------------
static __device__ __forceinline__ uint32_t smem_u32(const void* p) {
    uint32_t a;
    asm("{ .reg .u64 t; cvta.to.shared.u64 t, %1; cvt.u32.u64 %0, t; }"
        : "=r"(a) : "l"(p));
    return a;
}
static __device__ __forceinline__ void cp16(uint32_t s, const void* g) {
    asm volatile("cp.async.cg.shared.global [%0], [%1], 16;" :: "r"(s), "l"(g));
}
#define CP_COMMIT() asm volatile("cp.async.commit_group;" ::: "memory")
#define CP_WAIT(n)  asm volatile("cp.async.wait_group %0;" :: "n"(n) : "memory")
#define PAIR_BAR(id) asm volatile("bar.sync %0, 64;" :: "r"(id) : "memory")

static __device__ __forceinline__ float exp2_fast(float x) {
    float r; asm("ex2.approx.ftz.f32 %0, %1;" : "=f"(r) : "f"(x)); return r;
}
static __device__ __forceinline__ float lg2_fast(float x) {
    float r; asm("lg2.approx.f32 %0, %1;" : "=f"(r) : "f"(x)); return r;
}
static __device__ __forceinline__ float rcp_fast(float x) {
    float r; asm("rcp.approx.ftz.f32 %0, %1;" : "=f"(r) : "f"(x)); return r;
}
static __device__ __forceinline__ uint32_t f2tf32(float v) {
    uint32_t r; asm("cvt.rna.tf32.f32 %0, %1;" : "=r"(r) : "f"(v)); return r;
}
static __device__ __forceinline__ uint32_t lds32(const char* smem, uint32_t off) {
    return *reinterpret_cast<const uint32_t*>(smem + off);
}

// mma.sync m16n8k8 tf32
static __device__ __forceinline__ void mma_tf32(
    float* d, const uint32_t* a, uint32_t b0, uint32_t b1) {
    asm volatile(
        "mma.sync.aligned.m16n8k8.row.col.f32.tf32.tf32.f32 "
        "{%0,%1,%2,%3}, {%4,%5,%6,%7}, {%8,%9}, {%0,%1,%2,%3};"
        : "+f"(d[0]), "+f"(d[1]), "+f"(d[2]), "+f"(d[3])
        : "r"(a[0]), "r"(a[1]), "r"(a[2]), "r"(a[3]), "r"(b0), "r"(b1));
}

static __device__ __forceinline__ float expv(float z) {
    float w = fminf(fmaxf(z * C_SCALE_L2E, -C_CLAMP_L2E), C_CLAMP_L2E);
    return exp2_fast(w);
}
// mish(ln s): e^(ln s) == s exactly -> tanh(softplus) = ((1+s)^2-1)/((1+s)^2+1)
static __device__ __forceinline__ float mish_of_ln(float s) {
    float lse = C_LN2 * lg2_fast(s);
    float up  = s + 1.0f;
    float q   = up * up;
    return lse * (q - 1.0f) * rcp_fast(q + 1.0f);
}

// load one 16-row unit (4 KB contiguous in gmem), XOR-swizzled dst
static __device__ __forceinline__ void load_unit(
    uint32_t dst_base, const float* __restrict__ src, int lane) {
#pragma unroll
    for (int i = 0; i < 8; i++) {
        int idx = i * 32 + lane;            // 256 16B-chunks
        int r = idx >> 4, c = idx & 15;
        cp16(dst_base + (uint32_t)(r * 256 + ((c ^ (r & 7)) << 4)),
             src + (size_t)idx * 4);
    }
}

// ---------------- kernel ----------------
__global__ void __launch_bounds__(THREADS, 2) fused_lin_lse_mish(
    const float* __restrict__ x, const float* __restrict__ W,
    float* __restrict__ out) {
    extern __shared__ char smem[];
    const uint32_t sb = smem_u32(smem);
    const int tid  = threadIdx.x;
    const int lane = tid & 31;
    const int w    = tid >> 5;
    const int h    = w & 1;              // half: nb 0..3 (h=0) / 4..7 (h=1)
    const int pair = w >> 1;             // 0..3
    const int g    = lane >> 2;          // 0..7
    const int t    = lane & 3;           // 0..3
    const int barid = 1 + pair;

    const size_t prow0 = (size_t)blockIdx.x * (PAIRS * NUNITS * UNIT_ROWS)
                       + (size_t)pair * (NUNITS * UNIT_ROWS);
    const uint32_t ring = sb + SMEM_RING + (uint32_t)pair * RING_BYTES;

    // ---- prologue loads first (start DRAM early): warp h issues units h, h+2 ----
#pragma unroll
    for (int s = 0; s < NSLOTS; s++) {
        if ((s & 1) == h) {
            load_unit(ring + (uint32_t)s * UNIT_BYTES,
                      x + (prow0 + (size_t)s * UNIT_ROWS) * 64, lane);
            CP_COMMIT();
        }
    }

    // ---- build fragment-major W (FB): entry e=(kb*4+j)*32+lane holds
    //      {W[eg+2j*8][8kb+et], W[..][8kb+4+et], W[eg+(2j+1)*8][8kb+et], W[..][8kb+4+et]}
#pragma unroll
    for (int i = 0; i < 4; i++) {
        int e  = i * THREADS + tid;       // 1024 entries
        int el = e & 31, j = (e >> 5) & 3, kb = e >> 7;
        int eg = el >> 2, et = el & 3;
        int n0 = eg + 2 * j * 8, n1 = n0 + 8;
        int k0 = 8 * kb + et;
        uint4 v;
        v.x = f2tf32(W[n0 * 64 + k0]);
        v.y = f2tf32(W[n0 * 64 + k0 + 4]);
        v.z = f2tf32(W[n1 * 64 + k0]);
        v.w = f2tf32(W[n1 * 64 + k0 + 4]);
        *reinterpret_cast<uint4*>(smem + e * 16) = v;
    }
    __syncthreads();

    // ---- pull this warp's permanent B fragments: nb-half h -> j in {2h, 2h+1} ----
    uint32_t b[8][4][2];                  // [kb][nb_local][2]
#pragma unroll
    for (int kb = 0; kb < 8; kb++)
#pragma unroll
        for (int jj = 0; jj < 2; jj++) {
            uint4 bv = *reinterpret_cast<const uint4*>(
                smem + ((kb * 4 + (h * 2 + jj)) * 32 + lane) * 16);
            b[kb][jj * 2 + 0][0] = bv.x;
            b[kb][jj * 2 + 0][1] = bv.y;
            b[kb][jj * 2 + 1][0] = bv.z;
            b[kb][jj * 2 + 1][1] = bv.w;
        }

    const uint32_t pb = (uint32_t)(SMEM_PB + pair * 2 * PB_BYTES);
    const uint32_t tq = (uint32_t)(t * 4);

#pragma unroll
    for (int u = 0; u < NUNITS; u++) {
        // producer of unit u (warp u&1) guarantees its arrival, then pair-sync
        if ((u & 1) == h) {
            if (u < NUNITS - 2) { CP_WAIT(1); } else { CP_WAIT(0); }
        }
        PAIR_BAR(barid);

        const uint32_t Ab = (uint32_t)(SMEM_RING + pair * RING_BYTES
                                       + (u & (NSLOTS - 1)) * UNIT_BYTES);
        float acc[4][4];
#pragma unroll
        for (int nb = 0; nb < 4; nb++)
#pragma unroll
            for (int q = 0; q < 4; q++) acc[nb][q] = 0.0f;

#pragma unroll
        for (int kb = 0; kb < 8; kb++) {
            const uint32_t cx0 = (uint32_t)((((2 * kb) ^ g) << 4)) + tq;
            const uint32_t cx1 = (uint32_t)((((2 * kb + 1) ^ g) << 4)) + tq;
            uint32_t a[4];
            a[0] = lds32(smem, Ab + (uint32_t)(g * 256) + cx0);
            a[1] = lds32(smem, Ab + (uint32_t)((g + 8) * 256) + cx0);
            a[2] = lds32(smem, Ab + (uint32_t)(g * 256) + cx1);
            a[3] = lds32(smem, Ab + (uint32_t)((g + 8) * 256) + cx1);
#pragma unroll
            for (int nb = 0; nb < 4; nb++)
                mma_tf32(acc[nb], a, b[kb][nb][0], b[kb][nb][1]);
        }

        // ---- partial sums over this half's 32 columns ----
        float sl = 0.0f, sh = 0.0f;
#pragma unroll
        for (int nb = 0; nb < 4; nb++) {
            sl += expv(acc[nb][0]) + expv(acc[nb][1]);
            sh += expv(acc[nb][2]) + expv(acc[nb][3]);
        }
        sl += __shfl_xor_sync(0xFFFFFFFF, sl, 1);
        sl += __shfl_xor_sync(0xFFFFFFFF, sl, 2);
        sh += __shfl_xor_sync(0xFFFFFFFF, sh, 1);
        sh += __shfl_xor_sync(0xFFFFFFFF, sh, 2);

        const uint32_t pbu = pb + (uint32_t)((u & 1) * PB_BYTES);
        if (t == 0) {
            // writer h, rows g and g+8 (32 floats per pair: [h*? no] -> [writer][row])
            *reinterpret_cast<float*>(smem + pbu + (h * 16 + g) * 4)     = sl;
            *reinterpret_cast<float*>(smem + pbu + (h * 16 + 8 + g) * 4) = sh;
        }
        PAIR_BAR(barid);                   // exchange + ring-release for slot u

        // ---- finalize: warp h handles rows h*8 .. h*8+7 ----
        if (lane < 8) {
            int r = h * 8 + lane;
            float s = *reinterpret_cast<const float*>(smem + pbu + r * 4)
                    + *reinterpret_cast<const float*>(smem + pbu + (16 + r) * 4);
            out[prow0 + (size_t)u * UNIT_ROWS + r] = mish_of_ln(s);
        }

        // ---- issue unit u+4 into slot u%4 (producer = warp (u+4)&1 == u&1) ----
        if (u + NSLOTS < NUNITS && (u & 1) == h) {
            load_unit(ring + (uint32_t)(u & (NSLOTS - 1)) * UNIT_BYTES,
                      x + (prow0 + (size_t)(u + NSLOTS) * UNIT_ROWS) * 64, lane);
            CP_COMMIT();
        }
    }
}

// ---------------- launch ----------------
extern "C" void kernel_launch(void* const* d_in, const int* in_sizes, int n_in,
                              void* d_out, int out_size) {
    (void)in_sizes; (void)n_in; (void)out_size;
    const float* x = (const float*)d_in[0];
    const float* W = (const float*)d_in[1];
    float* out = (float*)d_out;

    cudaFuncSetAttribute(fused_lin_lse_mish,
                         cudaFuncAttributeMaxDynamicSharedMemorySize, SMEM_TOTAL);
    fused_lin_lse_mish<<<CTAS, THREADS, SMEM_TOTAL>>>(x, W, out);
}